// round 10
// baseline (speedup 1.0000x reference)
#include <cuda_runtime.h>
#include <cuda_bf16.h>
#include <math.h>
#include <stdint.h>

// ---------------------------------------------------------------------------
// Problem constants
// ---------------------------------------------------------------------------
#define BW      2048
#define NTOK    98
#define DIM     256
#define NH      8
#define HD      32
#define TBL     507
#define HID     512
#define M_ROWS  (BW * NTOK)    // 200704
#define MTILES  (M_ROWS / 128) // 1568

typedef unsigned long long ull;

// ---------------------------------------------------------------------------
// packed fp32x2 helpers
// ---------------------------------------------------------------------------
__device__ __forceinline__ ull ffma2(ull a, ull b, ull c) {
    ull d;
    asm("fma.rn.f32x2 %0, %1, %2, %3;" : "=l"(d) : "l"(a), "l"(b), "l"(c));
    return d;
}
__device__ __forceinline__ ull pack2(float x, float y) {
    ull r;
    asm("mov.b64 %0, {%1, %2};" : "=l"(r) : "f"(x), "f"(y));
    return r;
}
__device__ __forceinline__ float lo32(ull v) { return __uint_as_float((unsigned)v); }
__device__ __forceinline__ float hi32(ull v) { return __uint_as_float((unsigned)(v >> 32)); }

// ---------------------------------------------------------------------------
// mma / ldmatrix / cp.async helpers (arch-portable: sm_80+)
// ---------------------------------------------------------------------------
__device__ __forceinline__ uint32_t smem_u32(const void* p) {
    uint32_t a;
    asm("{ .reg .u64 t; cvta.to.shared.u64 t, %1; cvt.u32.u64 %0, t; }"
        : "=r"(a) : "l"(p));
    return a;
}

__device__ __forceinline__ void ldsm_x4(uint32_t* r, uint32_t addr) {
    asm volatile("ldmatrix.sync.aligned.m8n8.x4.shared.b16 {%0,%1,%2,%3}, [%4];"
                 : "=r"(r[0]), "=r"(r[1]), "=r"(r[2]), "=r"(r[3]) : "r"(addr));
}

__device__ __forceinline__ void mma16816(float* c, const uint32_t* a,
                                         uint32_t b0, uint32_t b1) {
    asm volatile("mma.sync.aligned.m16n8k16.row.col.f32.bf16.bf16.f32 "
                 "{%0,%1,%2,%3}, {%4,%5,%6,%7}, {%8,%9}, {%0,%1,%2,%3};"
                 : "+f"(c[0]), "+f"(c[1]), "+f"(c[2]), "+f"(c[3])
                 : "r"(a[0]), "r"(a[1]), "r"(a[2]), "r"(a[3]),
                   "r"(b0), "r"(b1));
}

#define CP16(dst, src) \
    asm volatile("cp.async.cg.shared.global [%0], [%1], 16;" \
                 :: "r"(dst), "l"(src) : "memory")
#define CP_COMMIT() asm volatile("cp.async.commit_group;" ::: "memory")
#define CP_WAIT1()  asm volatile("cp.async.wait_group 1;" ::: "memory")
#define CP_WAIT0()  asm volatile("cp.async.wait_group 0;" ::: "memory")

// ---------------------------------------------------------------------------
// Device scratch
// ---------------------------------------------------------------------------
__device__ float g_qkv[3ull * BW * NH * NTOK * HD];
__device__ __nv_bfloat16 g_oh[(size_t)M_ROWS * DIM];
__device__ __nv_bfloat16 g_ol[(size_t)M_ROWS * DIM];
__device__ __nv_bfloat16 g_wqh[768 * DIM];
__device__ __nv_bfloat16 g_wql[768 * DIM];
__device__ __nv_bfloat16 g_wph[DIM * DIM];
__device__ __nv_bfloat16 g_wpl[DIM * DIM];
__device__ float g_bt[TBL * NH];
__device__ float g_rpbT[NH * NTOK * NTOK];   // transposed: [h][j(key)][i(query)]

// ---------------------------------------------------------------------------
// hi/lo bf16 split
// ---------------------------------------------------------------------------
__device__ __forceinline__ void split_bf16(float x, unsigned short& h, unsigned short& l) {
    __nv_bfloat16 hb = __float2bfloat16(x);
    float hf = __bfloat162float(hb);
    __nv_bfloat16 lb = __float2bfloat16(x - hf);
    h = __bfloat16_as_ushort(hb);
    l = __bfloat16_as_ushort(lb);
}

__global__ void cvt_hilo4(const float4* __restrict__ s,
                          uint2* __restrict__ dh, uint2* __restrict__ dl, int n4)
{
    int i = blockIdx.x * blockDim.x + threadIdx.x;
    if (i >= n4) return;
    float4 v = s[i];
    unsigned short h0,h1,h2,h3,l0,l1,l2,l3;
    split_bf16(v.x, h0, l0);
    split_bf16(v.y, h1, l1);
    split_bf16(v.z, h2, l2);
    split_bf16(v.w, h3, l3);
    uint2 H, L;
    H.x = (uint32_t)h0 | ((uint32_t)h1 << 16);
    H.y = (uint32_t)h2 | ((uint32_t)h3 << 16);
    L.x = (uint32_t)l0 | ((uint32_t)l1 << 16);
    L.y = (uint32_t)l2 | ((uint32_t)l3 << 16);
    dh[i] = H;
    dl[i] = L;
}

// ---------------------------------------------------------------------------
// CPB MLP — 8 warps/block, weights staged in smem
// ---------------------------------------------------------------------------
__device__ __forceinline__ float rel_coord(float x, float w) {
    float t = x / (w - 1.0f + 1e-6f) * 8.0f;
    float l = log2f(fabsf(t) + 1.0f) * (1.0f / 3.0f);
    return (t > 0.0f) ? l : ((t < 0.0f) ? -l : 0.0f);
}

__global__ __launch_bounds__(256)
void cpb_mlp_kernel(const float* __restrict__ w1,
                    const float* __restrict__ b1,
                    const float* __restrict__ w2)
{
    __shared__ float s_w1[HID * 3];
    __shared__ float s_b1[HID];
    __shared__ float s_w2[NH * HID];

    int tid = threadIdx.x;
    for (int i = tid; i < HID * 3; i += 256) s_w1[i] = w1[i];
    for (int i = tid; i < HID; i += 256)     s_b1[i] = b1[i];
    for (int i = tid; i < NH * HID; i += 256) s_w2[i] = w2[i];
    __syncthreads();

    int gw = blockIdx.x * 8 + (tid >> 5);
    int lane = tid & 31;
    if (gw >= TBL) return;
    int a = gw / 169;
    int b = (gw / 13) % 13;
    int c = gw % 13;
    float c0 = rel_coord((float)(a - 1), 2.0f);
    float c1 = rel_coord((float)(b - 6), 7.0f);
    float c2 = rel_coord((float)(c - 6), 7.0f);
    float acc[NH];
#pragma unroll
    for (int h = 0; h < NH; h++) acc[h] = 0.0f;
    for (int j = lane; j < HID; j += 32) {
        float hv = s_w1[j*3+0]*c0 + s_w1[j*3+1]*c1 + s_w1[j*3+2]*c2 + s_b1[j];
        hv = fmaxf(hv, 0.0f);
#pragma unroll
        for (int h = 0; h < NH; h++) acc[h] += hv * s_w2[h*HID + j];
    }
#pragma unroll
    for (int h = 0; h < NH; h++) {
#pragma unroll
        for (int o = 16; o > 0; o >>= 1)
            acc[h] += __shfl_xor_sync(0xFFFFFFFFu, acc[h], o);
    }
    if (lane == 0) {
#pragma unroll
        for (int h = 0; h < NH; h++) g_bt[gw*NH + h] = acc[h];
    }
}

__global__ void rpb_kernel()
{
    int idx = blockIdx.x * blockDim.x + threadIdx.x;
    if (idx >= NH * NTOK * NTOK) return;
    int h = idx / (NTOK * NTOK);
    int r = idx % (NTOK * NTOK);
    int j = r / NTOK, i = r % NTOK;
    int di = i / 49, hi = (i / 7) % 7, wi = i % 7;
    int dj = j / 49, hj = (j / 7) % 7, wj = j % 7;
    int t = (di - dj + 1) * 169 + (hi - hj + 6) * 13 + (wi - wj + 6);
    float v = g_bt[t*NH + h];
    g_rpbT[idx] = 16.0f / (1.0f + __expf(-v));
}

// ---------------------------------------------------------------------------
// A-resident bf16x3 GEMM via mma.sync + cp.async.
// IS_QKV: A comes in as fp32 (x), split to hi/lo in-kernel while staging.
// else:   A comes in pre-split (Ah/Al, from attention) via cp.async.
// ---------------------------------------------------------------------------
#define AROW   528
#define A_MAT  (128 * AROW)
#define BROW   144
#define B_MAT  (128 * BROW)
#define OFF_B  (2 * A_MAT)
#define GEMM_SMEM (2 * A_MAT + 4 * B_MAT)

template<bool IS_QKV>
__global__ __launch_bounds__(256)
void gemm_mma(const float* __restrict__ Axf,
              const __nv_bfloat16* __restrict__ Ah,
              const __nv_bfloat16* __restrict__ Al,
              const __nv_bfloat16* __restrict__ Bh,
              const __nv_bfloat16* __restrict__ Bl,
              float* __restrict__ outp,
              const float* __restrict__ qb,
              const float* __restrict__ vb,
              const float* __restrict__ pb,
              int nTiles)
{
    extern __shared__ __align__(16) unsigned char smc[];
    const uint32_t sb  = smem_u32(smc);
    const uint32_t sAH = sb;
    const uint32_t sAL = sb + A_MAT;

    int tid  = threadIdx.x;
    int lane = tid & 31;
    int wid  = tid >> 5;
    int wm   = wid & 3;
    int wn   = wid >> 2;
    int m0   = blockIdx.x * 128;
    int nIter = nTiles * 4;

    auto issueB = [&](int it, int buf) {
        int nt = it >> 2, ck = it & 3;
        uint32_t bBH = sb + OFF_B + (uint32_t)buf * (2 * B_MAT);
        uint32_t bBL = bBH + B_MAT;
        const char* gBh = (const char*)Bh + (size_t)nt * 128 * 512 + (size_t)ck * 128;
        const char* gBl = (const char*)Bl + (size_t)nt * 128 * 512 + (size_t)ck * 128;
#pragma unroll
        for (int t = 0; t < 4; t++) {
            int cidx = tid + t * 256;
            int r = cidx >> 3, c = cidx & 7;
            uint32_t so = (uint32_t)r * BROW + (uint32_t)c * 16;
            size_t  go = (size_t)r * 512 + (size_t)c * 16;
            CP16(bBH + so, gBh + go);
            CP16(bBL + so, gBl + go);
        }
    };

    if (IS_QKV) {
        issueB(0, 0);
        CP_COMMIT();
        issueB(1, 1);
        CP_COMMIT();
        const float4* gA = (const float4*)(Axf + (size_t)m0 * DIM);
#pragma unroll 8
        for (int t = 0; t < 32; t++) {
            int idx = tid + t * 256;
            int r = idx >> 6, c = idx & 63;
            float4 v = gA[(size_t)r * 64 + c];
            unsigned short h0,h1,h2,h3,l0,l1,l2,l3;
            split_bf16(v.x, h0, l0);
            split_bf16(v.y, h1, l1);
            split_bf16(v.z, h2, l2);
            split_bf16(v.w, h3, l3);
            uint2 H, L;
            H.x = (uint32_t)h0 | ((uint32_t)h1 << 16);
            H.y = (uint32_t)h2 | ((uint32_t)h3 << 16);
            L.x = (uint32_t)l0 | ((uint32_t)l1 << 16);
            L.y = (uint32_t)l2 | ((uint32_t)l3 << 16);
            uint32_t so = (uint32_t)r * AROW + (uint32_t)c * 8;
            *(uint2*)(smc + so)         = H;
            *(uint2*)(smc + A_MAT + so) = L;
        }
        CP_WAIT1();
    } else {
        {
            const char* gAh = (const char*)Ah + (size_t)m0 * 512;
            const char* gAl = (const char*)Al + (size_t)m0 * 512;
#pragma unroll
            for (int t = 0; t < 16; t++) {
                int cidx = tid + t * 256;
                int r = cidx >> 5, c = cidx & 31;
                uint32_t so = (uint32_t)r * AROW + (uint32_t)c * 16;
                size_t  go = (size_t)r * 512 + (size_t)c * 16;
                CP16(sAH + so, gAh + go);
                CP16(sAL + so, gAl + go);
            }
        }
        issueB(0, 0);
        CP_COMMIT();
        issueB(1, 1);
        CP_COMMIT();
        CP_WAIT1();
    }
    __syncthreads();

    int a_row = wm*32 + (lane & 7) + ((lane >> 3) & 1) * 8;
    int a_chk = (lane >> 4);
    int b_row = wn*64 + (lane & 7) + ((lane >> 4) & 1) * 8;
    int b_chk = (lane >> 3) & 1;

    float acc[2][8][4];
#pragma unroll
    for (int i = 0; i < 2; i++)
#pragma unroll
        for (int j = 0; j < 8; j++)
#pragma unroll
            for (int k = 0; k < 4; k++) acc[i][j][k] = 0.0f;

    const size_t tstride = (size_t)BW * NH * NTOK * HD;

    for (int it = 0; it < nIter; it++) {
        int buf = it & 1;
        int ck  = it & 3;
        uint32_t bBH = sb + OFF_B + (uint32_t)buf * (2 * B_MAT);
        uint32_t bBL = bBH + B_MAT;

#pragma unroll
        for (int kk = 0; kk < 4; kk++) {
            int kkg = ck * 4 + kk;
            uint32_t ah[2][4], al[2][4];
#pragma unroll
            for (int mt = 0; mt < 2; mt++) {
                uint32_t off = (uint32_t)(a_row + mt*16) * AROW
                             + (uint32_t)(a_chk + 2*kkg) * 16;
                ldsm_x4(ah[mt], sAH + off);
                ldsm_x4(al[mt], sAL + off);
            }
            uint32_t bh4[4][4], bl4[4][4];
#pragma unroll
            for (int nn = 0; nn < 4; nn++) {
                uint32_t off = (uint32_t)(b_row + nn*16) * BROW
                             + (uint32_t)(b_chk + 2*kk) * 16;
                ldsm_x4(bh4[nn], bBH + off);
                ldsm_x4(bl4[nn], bBL + off);
            }
#pragma unroll
            for (int mt = 0; mt < 2; mt++)
#pragma unroll
                for (int nt8 = 0; nt8 < 8; nt8++) {
                    int pr = nt8 >> 1, w2 = (nt8 & 1) * 2;
                    mma16816(acc[mt][nt8], ah[mt], bh4[pr][w2], bh4[pr][w2+1]);
                    mma16816(acc[mt][nt8], ah[mt], bl4[pr][w2], bl4[pr][w2+1]);
                    mma16816(acc[mt][nt8], al[mt], bh4[pr][w2], bh4[pr][w2+1]);
                }
        }

        if (ck == 3) {
            int nt = it >> 2;
            int n0 = nt * 128;
#pragma unroll
            for (int mt = 0; mt < 2; mt++) {
                int rA = m0 + wm*32 + mt*16 + (lane >> 2);
#pragma unroll
                for (int nt8 = 0; nt8 < 8; nt8++) {
                    int n = n0 + wn*64 + nt8*8 + (lane & 3) * 2;
                    if (IS_QKV) {
                        int which = n >> 8;
                        int h = (n >> 5) & 7;
                        int d = n & 31;
                        float2 bv = make_float2(0.f, 0.f);
                        if (which == 0)      bv = *(const float2*)(qb + (n & 255));
                        else if (which == 2) bv = *(const float2*)(vb + (n & 255));
                        {
                            int bwin = rA / NTOK, tok = rA - bwin * NTOK;
                            float* dst = g_qkv + (size_t)which * tstride
                                       + (((size_t)bwin * NH + h) * NTOK + tok) * HD + d;
                            *(float2*)dst = make_float2(acc[mt][nt8][0] + bv.x,
                                                        acc[mt][nt8][1] + bv.y);
                        }
                        {
                            int r2 = rA + 8;
                            int bwin = r2 / NTOK, tok = r2 - bwin * NTOK;
                            float* dst = g_qkv + (size_t)which * tstride
                                       + (((size_t)bwin * NH + h) * NTOK + tok) * HD + d;
                            *(float2*)dst = make_float2(acc[mt][nt8][2] + bv.x,
                                                        acc[mt][nt8][3] + bv.y);
                        }
                    } else {
                        float2 bv = *(const float2*)(pb + n);
                        *(float2*)(outp + (size_t)rA * DIM + n) =
                            make_float2(acc[mt][nt8][0] + bv.x, acc[mt][nt8][1] + bv.y);
                        *(float2*)(outp + (size_t)(rA + 8) * DIM + n) =
                            make_float2(acc[mt][nt8][2] + bv.x, acc[mt][nt8][3] + bv.y);
                    }
                    acc[mt][nt8][0] = 0.f; acc[mt][nt8][1] = 0.f;
                    acc[mt][nt8][2] = 0.f; acc[mt][nt8][3] = 0.f;
                }
            }
        }

        if (it + 1 >= nIter) break;
        __syncthreads();
        if (it + 2 < nIter) {
            issueB(it + 2, buf);
            CP_COMMIT();
            CP_WAIT1();
        } else {
            CP_WAIT0();
        }
        __syncthreads();
    }
}

// ---------------------------------------------------------------------------
// fused cosine attention — exact R6 version (best measured).
// Single-pass, static-max softmax, 1 query/thread, 128 threads, 28 KB smem.
// ---------------------------------------------------------------------------
#define QPAD 36
#define ATTN_SMEM (2 * NTOK * QPAD * 4)

__global__ __launch_bounds__(128)
void attn_kernel(const float* __restrict__ logit_scale)
{
    extern __shared__ float sm[];
    float* ks = sm;
    float* vs = sm + NTOK * QPAD;

    int bh = blockIdx.x;
    int b = bh >> 3;
    int h = bh & 7;
    int tid = threadIdx.x;

    const size_t tensor_stride = (size_t)BW * NH * NTOK * HD;
    size_t base = ((size_t)b * NH + h) * (NTOK * HD);
    const float* Q  = g_qkv + base;
    const float* Kp = g_qkv + tensor_stride + base;
    const float* Vp = g_qkv + 2 * tensor_stride + base;
    const float* rpbT_h = g_rpbT + (size_t)h * (NTOK * NTOK);

    for (int idx = tid; idx < NTOK * HD; idx += 128) {
        int r = idx >> 5, d = idx & 31;
        ks[r*QPAD + d] = Kp[idx];
        vs[r*QPAD + d] = Vp[idx];
    }
    __syncthreads();

    float scale = __expf(fminf(logit_scale[h], 4.6051702f));
    float smax = scale + 16.0f;

    int i = tid;
    ull q2[16];
    if (i < NTOK) {
        const float4* Qr = (const float4*)(Q + (size_t)i * HD);
        float qr[HD];
        float nq = 0.f;
#pragma unroll
        for (int c = 0; c < 8; c++) {
            float4 t = Qr[c];
            qr[c*4+0] = t.x; qr[c*4+1] = t.y; qr[c*4+2] = t.z; qr[c*4+3] = t.w;
            nq += t.x*t.x + t.y*t.y + t.z*t.z + t.w*t.w;
        }
        float rq = scale / fmaxf(sqrtf(nq), 1e-12f);
#pragma unroll
        for (int c = 0; c < 16; c++)
            q2[c] = pack2(qr[c*2] * rq, qr[c*2+1] * rq);

        float nk = 0.f;
#pragma unroll
        for (int d = 0; d < HD; d++) {
            float k = ks[i*QPAD + d];
            nk += k * k;
        }
        float rk = 1.0f / fmaxf(sqrtf(nk), 1e-12f);
#pragma unroll
        for (int c = 0; c < 8; c++) {
            float4 k4 = *(float4*)&ks[i*QPAD + c*4];
            k4.x *= rk; k4.y *= rk; k4.z *= rk; k4.w *= rk;
            *(float4*)&ks[i*QPAD + c*4] = k4;
        }
    }
    __syncthreads();

    if (i < NTOK) {
        float sum = 0.f;
        ull accv2[16];
#pragma unroll
        for (int c = 0; c < 16; c++) accv2[c] = 0ull;

        for (int j = 0; j < NTOK; j++) {
            const ulonglong2* kr = (const ulonglong2*)(ks + j*QPAD);
            ull s2a = 0ull, s2b = 0ull;
#pragma unroll
            for (int c = 0; c < 8; c += 2) {
                ulonglong2 ka = kr[c];
                ulonglong2 kb = kr[c+1];
                s2a = ffma2(q2[c*2+0], ka.x, s2a);
                s2b = ffma2(q2[c*2+1], ka.y, s2b);
                s2a = ffma2(q2[c*2+2], kb.x, s2a);
                s2b = ffma2(q2[c*2+3], kb.y, s2b);
            }
            float s = lo32(s2a) + hi32(s2a) + lo32(s2b) + hi32(s2b)
                    + rpbT_h[j * NTOK + i];
            float e = __expf(s - smax);
            sum += e;
            ull p2 = pack2(e, e);
            const ulonglong2* vr = (const ulonglong2*)(vs + j*QPAD);
#pragma unroll
            for (int c = 0; c < 8; c++) {
                ulonglong2 v2 = vr[c];
                accv2[c*2+0] = ffma2(p2, v2.x, accv2[c*2+0]);
                accv2[c*2+1] = ffma2(p2, v2.y, accv2[c*2+1]);
            }
        }
        float inv = 1.0f / sum;

        size_t row = ((size_t)b * NTOK + i) * DIM + (size_t)h * HD;
        uint32_t* ohp = (uint32_t*)(g_oh + row);
        uint32_t* olp = (uint32_t*)(g_ol + row);
#pragma unroll
        for (int c = 0; c < 16; c++) {
            float v0 = lo32(accv2[c]) * inv;
            float v1 = hi32(accv2[c]) * inv;
            unsigned short h0, h1, l0, l1;
            split_bf16(v0, h0, l0);
            split_bf16(v1, h1, l1);
            ohp[c] = (uint32_t)h0 | ((uint32_t)h1 << 16);
            olp[c] = (uint32_t)l0 | ((uint32_t)l1 << 16);
        }
    }
}

// ---------------------------------------------------------------------------
// kernel_launch — order chosen so launch index 3 = gemm_mma<true> (profiled)
// ---------------------------------------------------------------------------
extern "C" void kernel_launch(void* const* d_in, const int* in_sizes, int n_in,
                              void* d_out, int out_size)
{
    const float* x           = (const float*)d_in[0];
    const float* qkv_w       = (const float*)d_in[1];
    const float* q_bias      = (const float*)d_in[2];
    const float* v_bias      = (const float*)d_in[3];
    const float* logit_scale = (const float*)d_in[4];
    const float* cpb_w1      = (const float*)d_in[5];
    const float* cpb_b1      = (const float*)d_in[6];
    const float* cpb_w2      = (const float*)d_in[7];
    const float* proj_w      = (const float*)d_in[8];
    const float* proj_b      = (const float*)d_in[9];
    float* out = (float*)d_out;

    __nv_bfloat16 *oh, *ol, *wqh, *wql, *wph, *wpl;
    cudaGetSymbolAddress((void**)&oh,  g_oh);
    cudaGetSymbolAddress((void**)&ol,  g_ol);
    cudaGetSymbolAddress((void**)&wqh, g_wqh);
    cudaGetSymbolAddress((void**)&wql, g_wql);
    cudaGetSymbolAddress((void**)&wph, g_wph);
    cudaGetSymbolAddress((void**)&wpl, g_wpl);

    static bool attr_set = false;
    if (!attr_set) {
        cudaFuncSetAttribute(attn_kernel,
                             cudaFuncAttributeMaxDynamicSharedMemorySize, ATTN_SMEM);
        cudaFuncSetAttribute(gemm_mma<true>,
                             cudaFuncAttributeMaxDynamicSharedMemorySize, GEMM_SMEM);
        cudaFuncSetAttribute(gemm_mma<false>,
                             cudaFuncAttributeMaxDynamicSharedMemorySize, GEMM_SMEM);
        attr_set = true;
    }

    // 0: weight cvt (qkv_w), 1: weight cvt (proj_w), 2: cpb
    cvt_hilo4<<<(768 * DIM / 4 + 255) / 256, 256>>>((const float4*)qkv_w,
                                                    (uint2*)wqh, (uint2*)wql, 768 * DIM / 4);
    cvt_hilo4<<<(DIM * DIM / 4 + 255) / 256, 256>>>((const float4*)proj_w,
                                                    (uint2*)wph, (uint2*)wpl, DIM * DIM / 4);
    cpb_mlp_kernel<<<(TBL + 7) / 8, 256>>>(cpb_w1, cpb_b1, cpb_w2);

    // 3: QKV GEMM  <-- profiled launch index
    gemm_mma<true><<<MTILES, 256, GEMM_SMEM>>>(x, nullptr, nullptr, wqh, wql,
                                               nullptr, q_bias, v_bias, nullptr, 6);

    // 4: rpb (needs cpb only; must precede attn)
    rpb_kernel<<<(NH * NTOK * NTOK + 255) / 256, 256>>>();

    // 5: fused attention (R6 version)
    attn_kernel<<<BW * NH, 128, ATTN_SMEM>>>(logit_scale);

    // 6: proj GEMM
    gemm_mma<false><<<MTILES, 256, GEMM_SMEM>>>(nullptr, oh, ol, wph, wpl,
                                                out, nullptr, nullptr, proj_b, 2);
}

// round 11
// speedup vs baseline: 1.0887x; 1.0887x over previous
#include <cuda_runtime.h>
#include <cuda_bf16.h>
#include <math.h>
#include <stdint.h>

// ---------------------------------------------------------------------------
// Problem constants
// ---------------------------------------------------------------------------
#define BW      2048
#define NTOK    98
#define DIM     256
#define NH      8
#define HD      32
#define TBL     507
#define HID     512
#define M_ROWS  (BW * NTOK)    // 200704
#define MTILES  (M_ROWS / 128) // 1568

typedef unsigned long long ull;

// ---------------------------------------------------------------------------
// packed fp32x2 helpers
// ---------------------------------------------------------------------------
__device__ __forceinline__ ull ffma2(ull a, ull b, ull c) {
    ull d;
    asm("fma.rn.f32x2 %0, %1, %2, %3;" : "=l"(d) : "l"(a), "l"(b), "l"(c));
    return d;
}
__device__ __forceinline__ ull pack2(float x, float y) {
    ull r;
    asm("mov.b64 %0, {%1, %2};" : "=l"(r) : "f"(x), "f"(y));
    return r;
}
__device__ __forceinline__ float lo32(ull v) { return __uint_as_float((unsigned)v); }
__device__ __forceinline__ float hi32(ull v) { return __uint_as_float((unsigned)(v >> 32)); }

// ---------------------------------------------------------------------------
// mma / ldmatrix / cp.async helpers (arch-portable: sm_80+)
// ---------------------------------------------------------------------------
__device__ __forceinline__ uint32_t smem_u32(const void* p) {
    uint32_t a;
    asm("{ .reg .u64 t; cvta.to.shared.u64 t, %1; cvt.u32.u64 %0, t; }"
        : "=r"(a) : "l"(p));
    return a;
}

__device__ __forceinline__ void ldsm_x4(uint32_t* r, uint32_t addr) {
    asm volatile("ldmatrix.sync.aligned.m8n8.x4.shared.b16 {%0,%1,%2,%3}, [%4];"
                 : "=r"(r[0]), "=r"(r[1]), "=r"(r[2]), "=r"(r[3]) : "r"(addr));
}

__device__ __forceinline__ void mma16816(float* c, const uint32_t* a,
                                         uint32_t b0, uint32_t b1) {
    asm volatile("mma.sync.aligned.m16n8k16.row.col.f32.bf16.bf16.f32 "
                 "{%0,%1,%2,%3}, {%4,%5,%6,%7}, {%8,%9}, {%0,%1,%2,%3};"
                 : "+f"(c[0]), "+f"(c[1]), "+f"(c[2]), "+f"(c[3])
                 : "r"(a[0]), "r"(a[1]), "r"(a[2]), "r"(a[3]),
                   "r"(b0), "r"(b1));
}

#define CP16(dst, src) \
    asm volatile("cp.async.cg.shared.global [%0], [%1], 16;" \
                 :: "r"(dst), "l"(src) : "memory")
#define CP_COMMIT() asm volatile("cp.async.commit_group;" ::: "memory")
#define CP_WAIT2()  asm volatile("cp.async.wait_group 2;" ::: "memory")
#define CP_WAIT1()  asm volatile("cp.async.wait_group 1;" ::: "memory")
#define CP_WAIT0()  asm volatile("cp.async.wait_group 0;" ::: "memory")

// ---------------------------------------------------------------------------
// Device scratch
// ---------------------------------------------------------------------------
__device__ float g_qkv[3ull * BW * NH * NTOK * HD];
__device__ __nv_bfloat16 g_xh[(size_t)M_ROWS * DIM];
__device__ __nv_bfloat16 g_xl[(size_t)M_ROWS * DIM];
__device__ __nv_bfloat16 g_oh[(size_t)M_ROWS * DIM];
__device__ __nv_bfloat16 g_ol[(size_t)M_ROWS * DIM];
__device__ __nv_bfloat16 g_wqh[768 * DIM];
__device__ __nv_bfloat16 g_wql[768 * DIM];
__device__ __nv_bfloat16 g_wph[DIM * DIM];
__device__ __nv_bfloat16 g_wpl[DIM * DIM];
__device__ float g_bt[TBL * NH];
__device__ float g_rpbT[NH * NTOK * NTOK];   // transposed: [h][j(key)][i(query)]

// ---------------------------------------------------------------------------
// hi/lo bf16 split
// ---------------------------------------------------------------------------
__device__ __forceinline__ void split_bf16(float x, unsigned short& h, unsigned short& l) {
    __nv_bfloat16 hb = __float2bfloat16(x);
    float hf = __bfloat162float(hb);
    __nv_bfloat16 lb = __float2bfloat16(x - hf);
    h = __bfloat16_as_ushort(hb);
    l = __bfloat16_as_ushort(lb);
}

__global__ void cvt_hilo4(const float4* __restrict__ s,
                          uint2* __restrict__ dh, uint2* __restrict__ dl, int n4)
{
    int i = blockIdx.x * blockDim.x + threadIdx.x;
    if (i >= n4) return;
    float4 v = s[i];
    unsigned short h0,h1,h2,h3,l0,l1,l2,l3;
    split_bf16(v.x, h0, l0);
    split_bf16(v.y, h1, l1);
    split_bf16(v.z, h2, l2);
    split_bf16(v.w, h3, l3);
    uint2 H, L;
    H.x = (uint32_t)h0 | ((uint32_t)h1 << 16);
    H.y = (uint32_t)h2 | ((uint32_t)h3 << 16);
    L.x = (uint32_t)l0 | ((uint32_t)l1 << 16);
    L.y = (uint32_t)l2 | ((uint32_t)l3 << 16);
    dh[i] = H;
    dl[i] = L;
}

// ---------------------------------------------------------------------------
// CPB MLP + rpb
// ---------------------------------------------------------------------------
__device__ __forceinline__ float rel_coord(float x, float w) {
    float t = x / (w - 1.0f + 1e-6f) * 8.0f;
    float l = log2f(fabsf(t) + 1.0f) * (1.0f / 3.0f);
    return (t > 0.0f) ? l : ((t < 0.0f) ? -l : 0.0f);
}

__global__ __launch_bounds__(256)
void cpb_mlp_kernel(const float* __restrict__ w1,
                    const float* __restrict__ b1,
                    const float* __restrict__ w2)
{
    __shared__ float s_w1[HID * 3];
    __shared__ float s_b1[HID];
    __shared__ float s_w2[NH * HID];

    int tid = threadIdx.x;
    for (int i = tid; i < HID * 3; i += 256) s_w1[i] = w1[i];
    for (int i = tid; i < HID; i += 256)     s_b1[i] = b1[i];
    for (int i = tid; i < NH * HID; i += 256) s_w2[i] = w2[i];
    __syncthreads();

    int gw = blockIdx.x * 8 + (tid >> 5);
    int lane = tid & 31;
    if (gw >= TBL) return;
    int a = gw / 169;
    int b = (gw / 13) % 13;
    int c = gw % 13;
    float c0 = rel_coord((float)(a - 1), 2.0f);
    float c1 = rel_coord((float)(b - 6), 7.0f);
    float c2 = rel_coord((float)(c - 6), 7.0f);
    float acc[NH];
#pragma unroll
    for (int h = 0; h < NH; h++) acc[h] = 0.0f;
    for (int j = lane; j < HID; j += 32) {
        float hv = s_w1[j*3+0]*c0 + s_w1[j*3+1]*c1 + s_w1[j*3+2]*c2 + s_b1[j];
        hv = fmaxf(hv, 0.0f);
#pragma unroll
        for (int h = 0; h < NH; h++) acc[h] += hv * s_w2[h*HID + j];
    }
#pragma unroll
    for (int h = 0; h < NH; h++) {
#pragma unroll
        for (int o = 16; o > 0; o >>= 1)
            acc[h] += __shfl_xor_sync(0xFFFFFFFFu, acc[h], o);
    }
    if (lane == 0) {
#pragma unroll
        for (int h = 0; h < NH; h++) g_bt[gw*NH + h] = acc[h];
    }
}

__global__ void rpb_kernel()
{
    int idx = blockIdx.x * blockDim.x + threadIdx.x;
    if (idx >= NH * NTOK * NTOK) return;
    int h = idx / (NTOK * NTOK);
    int r = idx % (NTOK * NTOK);
    int j = r / NTOK, i = r % NTOK;
    int di = i / 49, hi = (i / 7) % 7, wi = i % 7;
    int dj = j / 49, hj = (j / 7) % 7, wj = j % 7;
    int t = (di - dj + 1) * 169 + (hi - hj + 6) * 13 + (wi - wj + 6);
    float v = g_bt[t*NH + h];
    g_rpbT[idx] = 16.0f / (1.0f + __expf(-v));
}

// ---------------------------------------------------------------------------
// bf16x3 GEMM — 128x128 tile, K32 chunks, 3-stage cp.async, 2 CTAs/SM.
// smem stage = 4 matrices (Ah,Al,Bh,Bl) x [128 rows x 32 bf16(64B)], XOR-swizzled.
// ---------------------------------------------------------------------------
#define MATB  8192                    // 128 * 64 bytes
#define STGB  (4 * MATB)              // 32768 per stage
#define NSTG  3
#define GEMM_SMEM (NSTG * STGB)       // 98304

__device__ __forceinline__ uint32_t sw64(int r, int c) {
    return (uint32_t)r * 64u + (uint32_t)((c ^ (r & 3)) << 4);
}

template<bool IS_QKV>
__global__ __launch_bounds__(256, 2)
void gemm_mma(const __nv_bfloat16* __restrict__ Ah,
              const __nv_bfloat16* __restrict__ Al,
              const __nv_bfloat16* __restrict__ Bh,
              const __nv_bfloat16* __restrict__ Bl,
              float* __restrict__ outp,
              const float* __restrict__ qb,
              const float* __restrict__ vb,
              const float* __restrict__ pb)
{
    extern __shared__ __align__(16) unsigned char smc[];
    const uint32_t sb = smem_u32(smc);

    int tid  = threadIdx.x;
    int lane = tid & 31;
    int wid  = tid >> 5;
    int wm   = wid & 3;
    int wn   = wid >> 2;
    int n0   = blockIdx.x * 128;
    int m0   = blockIdx.y * 128;

    const char* srcs[4] = {
        (const char*)Ah + (size_t)m0 * 512,
        (const char*)Al + (size_t)m0 * 512,
        (const char*)Bh + (size_t)n0 * 512,
        (const char*)Bl + (size_t)n0 * 512
    };

    auto issue = [&](int ck, int buf) {
        uint32_t st = sb + (uint32_t)buf * STGB;
#pragma unroll
        for (int t = 0; t < 8; t++) {
            int m = t >> 1;
            int s = tid + (t & 1) * 256;     // 0..511
            int r = s >> 2, c = s & 3;
            uint32_t dst = st + (uint32_t)m * MATB + sw64(r, c);
            const char* src = srcs[m] + (size_t)r * 512 + ck * 64 + c * 16;
            CP16(dst, src);
        }
    };

    issue(0, 0); CP_COMMIT();
    issue(1, 1); CP_COMMIT();
    issue(2, 2); CP_COMMIT();

    // ldmatrix lane geometry
    int aRow = wm * 32 + (lane & 15);                       // + mt*16
    int aC   = lane >> 4;                                    // + 2*kk
    int bRow = wn * 64 + (lane & 7) + ((lane >> 4) & 1) * 8; // + nn*16
    int bC   = (lane >> 3) & 1;                              // + 2*kk

    float acc[2][8][4];
#pragma unroll
    for (int i = 0; i < 2; i++)
#pragma unroll
        for (int j = 0; j < 8; j++)
#pragma unroll
            for (int k = 0; k < 4; k++) acc[i][j][k] = 0.0f;

    for (int c = 0; c < 8; c++) {
        if (c <= 5)      CP_WAIT2();
        else if (c == 6) CP_WAIT1();
        else             CP_WAIT0();
        __syncthreads();

        uint32_t st = sb + (uint32_t)(c % 3) * STGB;
        uint32_t stAH = st, stAL = st + MATB, stBH = st + 2*MATB, stBL = st + 3*MATB;

#pragma unroll
        for (int kk = 0; kk < 2; kk++) {
            uint32_t ah[2][4], al[2][4];
#pragma unroll
            for (int mt = 0; mt < 2; mt++) {
                int r = aRow + mt * 16;
                uint32_t off = sw64(r, aC + 2 * kk);
                ldsm_x4(ah[mt], stAH + off);
                ldsm_x4(al[mt], stAL + off);
            }
#pragma unroll
            for (int pr = 0; pr < 4; pr++) {
                int r = bRow + pr * 16;
                uint32_t off = sw64(r, bC + 2 * kk);
                uint32_t bh4[4], bl4[4];
                ldsm_x4(bh4, stBH + off);
                ldsm_x4(bl4, stBL + off);
#pragma unroll
                for (int mt = 0; mt < 2; mt++)
#pragma unroll
                    for (int hf = 0; hf < 2; hf++) {
                        int w2 = hf * 2;
                        float* a4 = acc[mt][pr * 2 + hf];
                        mma16816(a4, ah[mt], bh4[w2], bh4[w2+1]);
                        mma16816(a4, ah[mt], bl4[w2], bl4[w2+1]);
                        mma16816(a4, al[mt], bh4[w2], bh4[w2+1]);
                    }
            }
        }
        __syncthreads();
        if (c + 3 < 8) { issue(c + 3, c % 3); CP_COMMIT(); }
    }

    // ---------------- epilogue ----------------
    const size_t tstride = (size_t)BW * NH * NTOK * HD;
#pragma unroll
    for (int mt = 0; mt < 2; mt++) {
        int rA = m0 + wm*32 + mt*16 + (lane >> 2);
#pragma unroll
        for (int nt8 = 0; nt8 < 8; nt8++) {
            int n = n0 + wn*64 + nt8*8 + (lane & 3) * 2;
            if (IS_QKV) {
                int which = n >> 8;
                int h = (n >> 5) & 7;
                int d = n & 31;
                float2 bv = make_float2(0.f, 0.f);
                if (which == 0)      bv = *(const float2*)(qb + (n & 255));
                else if (which == 2) bv = *(const float2*)(vb + (n & 255));
                {
                    int bwin = rA / NTOK, tok = rA - bwin * NTOK;
                    float* dst = g_qkv + (size_t)which * tstride
                               + (((size_t)bwin * NH + h) * NTOK + tok) * HD + d;
                    *(float2*)dst = make_float2(acc[mt][nt8][0] + bv.x,
                                                acc[mt][nt8][1] + bv.y);
                }
                {
                    int r2 = rA + 8;
                    int bwin = r2 / NTOK, tok = r2 - bwin * NTOK;
                    float* dst = g_qkv + (size_t)which * tstride
                               + (((size_t)bwin * NH + h) * NTOK + tok) * HD + d;
                    *(float2*)dst = make_float2(acc[mt][nt8][2] + bv.x,
                                                acc[mt][nt8][3] + bv.y);
                }
            } else {
                float2 bv = *(const float2*)(pb + n);
                *(float2*)(outp + (size_t)rA * DIM + n) =
                    make_float2(acc[mt][nt8][0] + bv.x, acc[mt][nt8][1] + bv.y);
                *(float2*)(outp + (size_t)(rA + 8) * DIM + n) =
                    make_float2(acc[mt][nt8][2] + bv.x, acc[mt][nt8][3] + bv.y);
            }
        }
    }
}

// ---------------------------------------------------------------------------
// fused cosine attention — R6 version (best measured).
// ---------------------------------------------------------------------------
#define QPAD 36
#define ATTN_SMEM (2 * NTOK * QPAD * 4)

__global__ __launch_bounds__(128)
void attn_kernel(const float* __restrict__ logit_scale)
{
    extern __shared__ float sm[];
    float* ks = sm;
    float* vs = sm + NTOK * QPAD;

    int bh = blockIdx.x;
    int b = bh >> 3;
    int h = bh & 7;
    int tid = threadIdx.x;

    const size_t tensor_stride = (size_t)BW * NH * NTOK * HD;
    size_t base = ((size_t)b * NH + h) * (NTOK * HD);
    const float* Q  = g_qkv + base;
    const float* Kp = g_qkv + tensor_stride + base;
    const float* Vp = g_qkv + 2 * tensor_stride + base;
    const float* rpbT_h = g_rpbT + (size_t)h * (NTOK * NTOK);

    for (int idx = tid; idx < NTOK * HD; idx += 128) {
        int r = idx >> 5, d = idx & 31;
        ks[r*QPAD + d] = Kp[idx];
        vs[r*QPAD + d] = Vp[idx];
    }
    __syncthreads();

    float scale = __expf(fminf(logit_scale[h], 4.6051702f));
    float smax = scale + 16.0f;

    int i = tid;
    ull q2[16];
    if (i < NTOK) {
        const float4* Qr = (const float4*)(Q + (size_t)i * HD);
        float qr[HD];
        float nq = 0.f;
#pragma unroll
        for (int c = 0; c < 8; c++) {
            float4 t = Qr[c];
            qr[c*4+0] = t.x; qr[c*4+1] = t.y; qr[c*4+2] = t.z; qr[c*4+3] = t.w;
            nq += t.x*t.x + t.y*t.y + t.z*t.z + t.w*t.w;
        }
        float rq = scale / fmaxf(sqrtf(nq), 1e-12f);
#pragma unroll
        for (int c = 0; c < 16; c++)
            q2[c] = pack2(qr[c*2] * rq, qr[c*2+1] * rq);

        float nk = 0.f;
#pragma unroll
        for (int d = 0; d < HD; d++) {
            float k = ks[i*QPAD + d];
            nk += k * k;
        }
        float rk = 1.0f / fmaxf(sqrtf(nk), 1e-12f);
#pragma unroll
        for (int c = 0; c < 8; c++) {
            float4 k4 = *(float4*)&ks[i*QPAD + c*4];
            k4.x *= rk; k4.y *= rk; k4.z *= rk; k4.w *= rk;
            *(float4*)&ks[i*QPAD + c*4] = k4;
        }
    }
    __syncthreads();

    if (i < NTOK) {
        float sum = 0.f;
        ull accv2[16];
#pragma unroll
        for (int c = 0; c < 16; c++) accv2[c] = 0ull;

        for (int j = 0; j < NTOK; j++) {
            const ulonglong2* kr = (const ulonglong2*)(ks + j*QPAD);
            ull s2a = 0ull, s2b = 0ull;
#pragma unroll
            for (int c = 0; c < 8; c += 2) {
                ulonglong2 ka = kr[c];
                ulonglong2 kb = kr[c+1];
                s2a = ffma2(q2[c*2+0], ka.x, s2a);
                s2b = ffma2(q2[c*2+1], ka.y, s2b);
                s2a = ffma2(q2[c*2+2], kb.x, s2a);
                s2b = ffma2(q2[c*2+3], kb.y, s2b);
            }
            float s = lo32(s2a) + hi32(s2a) + lo32(s2b) + hi32(s2b)
                    + rpbT_h[j * NTOK + i];
            float e = __expf(s - smax);
            sum += e;
            ull p2 = pack2(e, e);
            const ulonglong2* vr = (const ulonglong2*)(vs + j*QPAD);
#pragma unroll
            for (int c = 0; c < 8; c++) {
                ulonglong2 v2 = vr[c];
                accv2[c*2+0] = ffma2(p2, v2.x, accv2[c*2+0]);
                accv2[c*2+1] = ffma2(p2, v2.y, accv2[c*2+1]);
            }
        }
        float inv = 1.0f / sum;

        size_t row = ((size_t)b * NTOK + i) * DIM + (size_t)h * HD;
        uint32_t* ohp = (uint32_t*)(g_oh + row);
        uint32_t* olp = (uint32_t*)(g_ol + row);
#pragma unroll
        for (int c = 0; c < 16; c++) {
            float v0 = lo32(accv2[c]) * inv;
            float v1 = hi32(accv2[c]) * inv;
            unsigned short h0, h1, l0, l1;
            split_bf16(v0, h0, l0);
            split_bf16(v1, h1, l1);
            ohp[c] = (uint32_t)h0 | ((uint32_t)h1 << 16);
            olp[c] = (uint32_t)l0 | ((uint32_t)l1 << 16);
        }
    }
}

// ---------------------------------------------------------------------------
// kernel_launch — launch index 3 = QKV GEMM (profiled)
// ---------------------------------------------------------------------------
extern "C" void kernel_launch(void* const* d_in, const int* in_sizes, int n_in,
                              void* d_out, int out_size)
{
    const float* x           = (const float*)d_in[0];
    const float* qkv_w       = (const float*)d_in[1];
    const float* q_bias      = (const float*)d_in[2];
    const float* v_bias      = (const float*)d_in[3];
    const float* logit_scale = (const float*)d_in[4];
    const float* cpb_w1      = (const float*)d_in[5];
    const float* cpb_b1      = (const float*)d_in[6];
    const float* cpb_w2      = (const float*)d_in[7];
    const float* proj_w      = (const float*)d_in[8];
    const float* proj_b      = (const float*)d_in[9];
    float* out = (float*)d_out;

    __nv_bfloat16 *xh, *xl, *oh, *ol, *wqh, *wql, *wph, *wpl;
    cudaGetSymbolAddress((void**)&xh,  g_xh);
    cudaGetSymbolAddress((void**)&xl,  g_xl);
    cudaGetSymbolAddress((void**)&oh,  g_oh);
    cudaGetSymbolAddress((void**)&ol,  g_ol);
    cudaGetSymbolAddress((void**)&wqh, g_wqh);
    cudaGetSymbolAddress((void**)&wql, g_wql);
    cudaGetSymbolAddress((void**)&wph, g_wph);
    cudaGetSymbolAddress((void**)&wpl, g_wpl);

    static bool attr_set = false;
    if (!attr_set) {
        cudaFuncSetAttribute(attn_kernel,
                             cudaFuncAttributeMaxDynamicSharedMemorySize, ATTN_SMEM);
        cudaFuncSetAttribute(gemm_mma<true>,
                             cudaFuncAttributeMaxDynamicSharedMemorySize, GEMM_SMEM);
        cudaFuncSetAttribute(gemm_mma<false>,
                             cudaFuncAttributeMaxDynamicSharedMemorySize, GEMM_SMEM);
        attr_set = true;
    }

    // 0: split x, 1: split qkv_w, 2: split proj_w
    {
        int n4 = (M_ROWS * DIM) / 4;
        cvt_hilo4<<<(n4 + 255) / 256, 256>>>((const float4*)x, (uint2*)xh, (uint2*)xl, n4);
    }
    cvt_hilo4<<<(768 * DIM / 4 + 255) / 256, 256>>>((const float4*)qkv_w,
                                                    (uint2*)wqh, (uint2*)wql, 768 * DIM / 4);
    cvt_hilo4<<<(DIM * DIM / 4 + 255) / 256, 256>>>((const float4*)proj_w,
                                                    (uint2*)wph, (uint2*)wpl, DIM * DIM / 4);

    // 3: QKV GEMM  <-- profiled launch index
    {
        dim3 grid(6, MTILES);
        gemm_mma<true><<<grid, 256, GEMM_SMEM>>>(xh, xl, wqh, wql,
                                                 nullptr, q_bias, v_bias, nullptr);
    }

    // 4: cpb, 5: rpb
    cpb_mlp_kernel<<<(TBL + 7) / 8, 256>>>(cpb_w1, cpb_b1, cpb_w2);
    rpb_kernel<<<(NH * NTOK * NTOK + 255) / 256, 256>>>();

    // 6: fused attention
    attn_kernel<<<BW * NH, 128, ATTN_SMEM>>>(logit_scale);

    // 7: proj GEMM
    {
        dim3 grid(2, MTILES);
        gemm_mma<false><<<grid, 256, GEMM_SMEM>>>(oh, ol, wph, wpl,
                                                  out, nullptr, nullptr, proj_b);
    }
}

// round 12
// speedup vs baseline: 1.2663x; 1.1631x over previous
#include <cuda_runtime.h>
#include <cuda_bf16.h>
#include <cuda_fp16.h>
#include <math.h>
#include <stdint.h>

// ---------------------------------------------------------------------------
// Problem constants
// ---------------------------------------------------------------------------
#define BW      2048
#define NTOK    98
#define DIM     256
#define NH      8
#define HD      32
#define TBL     507
#define HID     512
#define M_ROWS  (BW * NTOK)    // 200704
#define MTILES  (M_ROWS / 128) // 1568

typedef unsigned long long ull;

// ---------------------------------------------------------------------------
// packed fp32x2 helpers
// ---------------------------------------------------------------------------
__device__ __forceinline__ ull ffma2(ull a, ull b, ull c) {
    ull d;
    asm("fma.rn.f32x2 %0, %1, %2, %3;" : "=l"(d) : "l"(a), "l"(b), "l"(c));
    return d;
}
__device__ __forceinline__ ull pack2(float x, float y) {
    ull r;
    asm("mov.b64 %0, {%1, %2};" : "=l"(r) : "f"(x), "f"(y));
    return r;
}
__device__ __forceinline__ float lo32(ull v) { return __uint_as_float((unsigned)v); }
__device__ __forceinline__ float hi32(ull v) { return __uint_as_float((unsigned)(v >> 32)); }

// ---------------------------------------------------------------------------
// mma / ldmatrix / cp.async helpers (arch-portable: sm_80+)
// ---------------------------------------------------------------------------
__device__ __forceinline__ uint32_t smem_u32(const void* p) {
    uint32_t a;
    asm("{ .reg .u64 t; cvta.to.shared.u64 t, %1; cvt.u32.u64 %0, t; }"
        : "=r"(a) : "l"(p));
    return a;
}

__device__ __forceinline__ void ldsm_x4(uint32_t* r, uint32_t addr) {
    asm volatile("ldmatrix.sync.aligned.m8n8.x4.shared.b16 {%0,%1,%2,%3}, [%4];"
                 : "=r"(r[0]), "=r"(r[1]), "=r"(r[2]), "=r"(r[3]) : "r"(addr));
}

// fp16 MMA, fp32 accumulate
__device__ __forceinline__ void mma16816h(float* c, const uint32_t* a,
                                          uint32_t b0, uint32_t b1) {
    asm volatile("mma.sync.aligned.m16n8k16.row.col.f32.f16.f16.f32 "
                 "{%0,%1,%2,%3}, {%4,%5,%6,%7}, {%8,%9}, {%0,%1,%2,%3};"
                 : "+f"(c[0]), "+f"(c[1]), "+f"(c[2]), "+f"(c[3])
                 : "r"(a[0]), "r"(a[1]), "r"(a[2]), "r"(a[3]),
                   "r"(b0), "r"(b1));
}

#define CP16(dst, src) \
    asm volatile("cp.async.cg.shared.global [%0], [%1], 16;" \
                 :: "r"(dst), "l"(src) : "memory")
#define CP_COMMIT() asm volatile("cp.async.commit_group;" ::: "memory")
#define CP_WAIT2()  asm volatile("cp.async.wait_group 2;" ::: "memory")
#define CP_WAIT1()  asm volatile("cp.async.wait_group 1;" ::: "memory")
#define CP_WAIT0()  asm volatile("cp.async.wait_group 0;" ::: "memory")

// ---------------------------------------------------------------------------
// Device scratch
// ---------------------------------------------------------------------------
__device__ float g_qkv[3ull * BW * NH * NTOK * HD];
__device__ __half g_xh[(size_t)M_ROWS * DIM];
__device__ __half g_xl[(size_t)M_ROWS * DIM];
__device__ __half g_oh[(size_t)M_ROWS * DIM];
__device__ __half g_ol[(size_t)M_ROWS * DIM];
__device__ __half g_wq[768 * DIM];
__device__ __half g_wp[DIM * DIM];
__device__ float g_bt[TBL * NH];
__device__ float g_rpbT[NH * NTOK * NTOK];   // transposed: [h][j(key)][i(query)]

// ---------------------------------------------------------------------------
// fp16 hi/lo split + single conversion
// ---------------------------------------------------------------------------
__device__ __forceinline__ void split_f16(float x, unsigned short& h, unsigned short& l) {
    __half hb = __float2half_rn(x);
    float hf = __half2float(hb);
    __half lb = __float2half_rn(x - hf);
    h = __half_as_ushort(hb);
    l = __half_as_ushort(lb);
}

__global__ void cvt_hilo4_f16(const float4* __restrict__ s,
                              uint2* __restrict__ dh, uint2* __restrict__ dl, int n4)
{
    int i = blockIdx.x * blockDim.x + threadIdx.x;
    if (i >= n4) return;
    float4 v = s[i];
    unsigned short h0,h1,h2,h3,l0,l1,l2,l3;
    split_f16(v.x, h0, l0);
    split_f16(v.y, h1, l1);
    split_f16(v.z, h2, l2);
    split_f16(v.w, h3, l3);
    uint2 H, L;
    H.x = (uint32_t)h0 | ((uint32_t)h1 << 16);
    H.y = (uint32_t)h2 | ((uint32_t)h3 << 16);
    L.x = (uint32_t)l0 | ((uint32_t)l1 << 16);
    L.y = (uint32_t)l2 | ((uint32_t)l3 << 16);
    dh[i] = H;
    dl[i] = L;
}

__global__ void cvt_f16_4(const float4* __restrict__ s,
                          uint2* __restrict__ d, int n4)
{
    int i = blockIdx.x * blockDim.x + threadIdx.x;
    if (i >= n4) return;
    float4 v = s[i];
    __half2 p0 = __floats2half2_rn(v.x, v.y);
    __half2 p1 = __floats2half2_rn(v.z, v.w);
    uint2 o;
    o.x = *(uint32_t*)&p0;
    o.y = *(uint32_t*)&p1;
    d[i] = o;
}

// ---------------------------------------------------------------------------
// CPB MLP + rpb
// ---------------------------------------------------------------------------
__device__ __forceinline__ float rel_coord(float x, float w) {
    float t = x / (w - 1.0f + 1e-6f) * 8.0f;
    float l = log2f(fabsf(t) + 1.0f) * (1.0f / 3.0f);
    return (t > 0.0f) ? l : ((t < 0.0f) ? -l : 0.0f);
}

__global__ __launch_bounds__(256)
void cpb_mlp_kernel(const float* __restrict__ w1,
                    const float* __restrict__ b1,
                    const float* __restrict__ w2)
{
    __shared__ float s_w1[HID * 3];
    __shared__ float s_b1[HID];
    __shared__ float s_w2[NH * HID];

    int tid = threadIdx.x;
    for (int i = tid; i < HID * 3; i += 256) s_w1[i] = w1[i];
    for (int i = tid; i < HID; i += 256)     s_b1[i] = b1[i];
    for (int i = tid; i < NH * HID; i += 256) s_w2[i] = w2[i];
    __syncthreads();

    int gw = blockIdx.x * 8 + (tid >> 5);
    int lane = tid & 31;
    if (gw >= TBL) return;
    int a = gw / 169;
    int b = (gw / 13) % 13;
    int c = gw % 13;
    float c0 = rel_coord((float)(a - 1), 2.0f);
    float c1 = rel_coord((float)(b - 6), 7.0f);
    float c2 = rel_coord((float)(c - 6), 7.0f);
    float acc[NH];
#pragma unroll
    for (int h = 0; h < NH; h++) acc[h] = 0.0f;
    for (int j = lane; j < HID; j += 32) {
        float hv = s_w1[j*3+0]*c0 + s_w1[j*3+1]*c1 + s_w1[j*3+2]*c2 + s_b1[j];
        hv = fmaxf(hv, 0.0f);
#pragma unroll
        for (int h = 0; h < NH; h++) acc[h] += hv * s_w2[h*HID + j];
    }
#pragma unroll
    for (int h = 0; h < NH; h++) {
#pragma unroll
        for (int o = 16; o > 0; o >>= 1)
            acc[h] += __shfl_xor_sync(0xFFFFFFFFu, acc[h], o);
    }
    if (lane == 0) {
#pragma unroll
        for (int h = 0; h < NH; h++) g_bt[gw*NH + h] = acc[h];
    }
}

__global__ void rpb_kernel()
{
    int idx = blockIdx.x * blockDim.x + threadIdx.x;
    if (idx >= NH * NTOK * NTOK) return;
    int h = idx / (NTOK * NTOK);
    int r = idx % (NTOK * NTOK);
    int j = r / NTOK, i = r % NTOK;
    int di = i / 49, hi = (i / 7) % 7, wi = i % 7;
    int dj = j / 49, hj = (j / 7) % 7, wj = j % 7;
    int t = (di - dj + 1) * 169 + (hi - hj + 6) * 13 + (wi - wj + 6);
    float v = g_bt[t*NH + h];
    g_rpbT[idx] = 16.0f / (1.0f + __expf(-v));
}

// ---------------------------------------------------------------------------
// fp16 2-pass GEMM — 128x128 tile, K32 chunks, 3-stage cp.async, 2 CTAs/SM.
// C = (Ah + Al) * Bf^T.  Stage = 3 matrices (Ah, Al, Bf) x [128 x 32 f16], swizzled.
// ---------------------------------------------------------------------------
#define MATB  8192                    // 128 * 64 bytes
#define STGB  (3 * MATB)              // 24576 per stage
#define NSTG  3
#define GEMM_SMEM (NSTG * STGB)       // 73728

__device__ __forceinline__ uint32_t sw64(int r, int c) {
    return (uint32_t)r * 64u + (uint32_t)((c ^ (r & 3)) << 4);
}

template<bool IS_QKV>
__global__ __launch_bounds__(256, 2)
void gemm_mma(const __half* __restrict__ Ah,
              const __half* __restrict__ Al,
              const __half* __restrict__ Bf,
              float* __restrict__ outp,
              const float* __restrict__ qb,
              const float* __restrict__ vb,
              const float* __restrict__ pb)
{
    extern __shared__ __align__(16) unsigned char smc[];
    const uint32_t sb = smem_u32(smc);

    int tid  = threadIdx.x;
    int lane = tid & 31;
    int wid  = tid >> 5;
    int wm   = wid & 3;
    int wn   = wid >> 2;
    int n0   = blockIdx.x * 128;
    int m0   = blockIdx.y * 128;

    const char* srcs[3] = {
        (const char*)Ah + (size_t)m0 * 512,
        (const char*)Al + (size_t)m0 * 512,
        (const char*)Bf + (size_t)n0 * 512
    };

    auto issue = [&](int ck, int buf) {
        uint32_t st = sb + (uint32_t)buf * STGB;
#pragma unroll
        for (int t = 0; t < 6; t++) {
            int m = t >> 1;
            int s = tid + (t & 1) * 256;     // 0..511
            int r = s >> 2, c = s & 3;
            uint32_t dst = st + (uint32_t)m * MATB + sw64(r, c);
            const char* src = srcs[m] + (size_t)r * 512 + ck * 64 + c * 16;
            CP16(dst, src);
        }
    };

    issue(0, 0); CP_COMMIT();
    issue(1, 1); CP_COMMIT();
    issue(2, 2); CP_COMMIT();

    int aRow = wm * 32 + (lane & 15);                       // + mt*16
    int aC   = lane >> 4;                                    // + 2*kk
    int bRow = wn * 64 + (lane & 7) + ((lane >> 4) & 1) * 8; // + pr*16
    int bC   = (lane >> 3) & 1;                              // + 2*kk

    float acc[2][8][4];
#pragma unroll
    for (int i = 0; i < 2; i++)
#pragma unroll
        for (int j = 0; j < 8; j++)
#pragma unroll
            for (int k = 0; k < 4; k++) acc[i][j][k] = 0.0f;

    for (int c = 0; c < 8; c++) {
        if (c <= 5)      CP_WAIT2();
        else if (c == 6) CP_WAIT1();
        else             CP_WAIT0();
        __syncthreads();

        uint32_t st = sb + (uint32_t)(c % 3) * STGB;
        uint32_t stAH = st, stAL = st + MATB, stBF = st + 2*MATB;

#pragma unroll
        for (int kk = 0; kk < 2; kk++) {
            uint32_t ah[2][4], al[2][4];
#pragma unroll
            for (int mt = 0; mt < 2; mt++) {
                int r = aRow + mt * 16;
                uint32_t off = sw64(r, aC + 2 * kk);
                ldsm_x4(ah[mt], stAH + off);
                ldsm_x4(al[mt], stAL + off);
            }
#pragma unroll
            for (int pr = 0; pr < 4; pr++) {
                int r = bRow + pr * 16;
                uint32_t off = sw64(r, bC + 2 * kk);
                uint32_t bf4[4];
                ldsm_x4(bf4, stBF + off);
#pragma unroll
                for (int mt = 0; mt < 2; mt++)
#pragma unroll
                    for (int hf = 0; hf < 2; hf++) {
                        int w2 = hf * 2;
                        float* a4 = acc[mt][pr * 2 + hf];
                        mma16816h(a4, ah[mt], bf4[w2], bf4[w2+1]);
                        mma16816h(a4, al[mt], bf4[w2], bf4[w2+1]);
                    }
            }
        }
        __syncthreads();
        if (c + 3 < 8) { issue(c + 3, c % 3); CP_COMMIT(); }
    }

    // ---------------- epilogue ----------------
    const size_t tstride = (size_t)BW * NH * NTOK * HD;
#pragma unroll
    for (int mt = 0; mt < 2; mt++) {
        int rA = m0 + wm*32 + mt*16 + (lane >> 2);
#pragma unroll
        for (int nt8 = 0; nt8 < 8; nt8++) {
            int n = n0 + wn*64 + nt8*8 + (lane & 3) * 2;
            if (IS_QKV) {
                int which = n >> 8;
                int h = (n >> 5) & 7;
                int d = n & 31;
                float2 bv = make_float2(0.f, 0.f);
                if (which == 0)      bv = *(const float2*)(qb + (n & 255));
                else if (which == 2) bv = *(const float2*)(vb + (n & 255));
                {
                    int bwin = rA / NTOK, tok = rA - bwin * NTOK;
                    float* dst = g_qkv + (size_t)which * tstride
                               + (((size_t)bwin * NH + h) * NTOK + tok) * HD + d;
                    *(float2*)dst = make_float2(acc[mt][nt8][0] + bv.x,
                                                acc[mt][nt8][1] + bv.y);
                }
                {
                    int r2 = rA + 8;
                    int bwin = r2 / NTOK, tok = r2 - bwin * NTOK;
                    float* dst = g_qkv + (size_t)which * tstride
                               + (((size_t)bwin * NH + h) * NTOK + tok) * HD + d;
                    *(float2*)dst = make_float2(acc[mt][nt8][2] + bv.x,
                                                acc[mt][nt8][3] + bv.y);
                }
            } else {
                float2 bv = *(const float2*)(pb + n);
                *(float2*)(outp + (size_t)rA * DIM + n) =
                    make_float2(acc[mt][nt8][0] + bv.x, acc[mt][nt8][1] + bv.y);
                *(float2*)(outp + (size_t)(rA + 8) * DIM + n) =
                    make_float2(acc[mt][nt8][2] + bv.x, acc[mt][nt8][3] + bv.y);
            }
        }
    }
}

// ---------------------------------------------------------------------------
// fused cosine attention — R6 structure; output stored as fp16 hi/lo.
// ---------------------------------------------------------------------------
#define QPAD 36
#define ATTN_SMEM (2 * NTOK * QPAD * 4)

__global__ __launch_bounds__(128)
void attn_kernel(const float* __restrict__ logit_scale)
{
    extern __shared__ float sm[];
    float* ks = sm;
    float* vs = sm + NTOK * QPAD;

    int bh = blockIdx.x;
    int b = bh >> 3;
    int h = bh & 7;
    int tid = threadIdx.x;

    const size_t tensor_stride = (size_t)BW * NH * NTOK * HD;
    size_t base = ((size_t)b * NH + h) * (NTOK * HD);
    const float* Q  = g_qkv + base;
    const float* Kp = g_qkv + tensor_stride + base;
    const float* Vp = g_qkv + 2 * tensor_stride + base;
    const float* rpbT_h = g_rpbT + (size_t)h * (NTOK * NTOK);

    for (int idx = tid; idx < NTOK * HD; idx += 128) {
        int r = idx >> 5, d = idx & 31;
        ks[r*QPAD + d] = Kp[idx];
        vs[r*QPAD + d] = Vp[idx];
    }
    __syncthreads();

    float scale = __expf(fminf(logit_scale[h], 4.6051702f));
    float smax = scale + 16.0f;

    int i = tid;
    ull q2[16];
    if (i < NTOK) {
        const float4* Qr = (const float4*)(Q + (size_t)i * HD);
        float qr[HD];
        float nq = 0.f;
#pragma unroll
        for (int c = 0; c < 8; c++) {
            float4 t = Qr[c];
            qr[c*4+0] = t.x; qr[c*4+1] = t.y; qr[c*4+2] = t.z; qr[c*4+3] = t.w;
            nq += t.x*t.x + t.y*t.y + t.z*t.z + t.w*t.w;
        }
        float rq = scale / fmaxf(sqrtf(nq), 1e-12f);
#pragma unroll
        for (int c = 0; c < 16; c++)
            q2[c] = pack2(qr[c*2] * rq, qr[c*2+1] * rq);

        float nk = 0.f;
#pragma unroll
        for (int d = 0; d < HD; d++) {
            float k = ks[i*QPAD + d];
            nk += k * k;
        }
        float rk = 1.0f / fmaxf(sqrtf(nk), 1e-12f);
#pragma unroll
        for (int c = 0; c < 8; c++) {
            float4 k4 = *(float4*)&ks[i*QPAD + c*4];
            k4.x *= rk; k4.y *= rk; k4.z *= rk; k4.w *= rk;
            *(float4*)&ks[i*QPAD + c*4] = k4;
        }
    }
    __syncthreads();

    if (i < NTOK) {
        float sum = 0.f;
        ull accv2[16];
#pragma unroll
        for (int c = 0; c < 16; c++) accv2[c] = 0ull;

        for (int j = 0; j < NTOK; j++) {
            const ulonglong2* kr = (const ulonglong2*)(ks + j*QPAD);
            ull s2a = 0ull, s2b = 0ull;
#pragma unroll
            for (int c = 0; c < 8; c += 2) {
                ulonglong2 ka = kr[c];
                ulonglong2 kb = kr[c+1];
                s2a = ffma2(q2[c*2+0], ka.x, s2a);
                s2b = ffma2(q2[c*2+1], ka.y, s2b);
                s2a = ffma2(q2[c*2+2], kb.x, s2a);
                s2b = ffma2(q2[c*2+3], kb.y, s2b);
            }
            float s = lo32(s2a) + hi32(s2a) + lo32(s2b) + hi32(s2b)
                    + rpbT_h[j * NTOK + i];
            float e = __expf(s - smax);
            sum += e;
            ull p2 = pack2(e, e);
            const ulonglong2* vr = (const ulonglong2*)(vs + j*QPAD);
#pragma unroll
            for (int c = 0; c < 8; c++) {
                ulonglong2 v2 = vr[c];
                accv2[c*2+0] = ffma2(p2, v2.x, accv2[c*2+0]);
                accv2[c*2+1] = ffma2(p2, v2.y, accv2[c*2+1]);
            }
        }
        float inv = 1.0f / sum;

        size_t row = ((size_t)b * NTOK + i) * DIM + (size_t)h * HD;
        uint32_t* ohp = (uint32_t*)(g_oh + row);
        uint32_t* olp = (uint32_t*)(g_ol + row);
#pragma unroll
        for (int c = 0; c < 16; c++) {
            float v0 = lo32(accv2[c]) * inv;
            float v1 = hi32(accv2[c]) * inv;
            unsigned short h0, h1, l0, l1;
            split_f16(v0, h0, l0);
            split_f16(v1, h1, l1);
            ohp[c] = (uint32_t)h0 | ((uint32_t)h1 << 16);
            olp[c] = (uint32_t)l0 | ((uint32_t)l1 << 16);
        }
    }
}

// ---------------------------------------------------------------------------
// kernel_launch — launch index 3 = QKV GEMM (profiled)
// ---------------------------------------------------------------------------
extern "C" void kernel_launch(void* const* d_in, const int* in_sizes, int n_in,
                              void* d_out, int out_size)
{
    const float* x           = (const float*)d_in[0];
    const float* qkv_w       = (const float*)d_in[1];
    const float* q_bias      = (const float*)d_in[2];
    const float* v_bias      = (const float*)d_in[3];
    const float* logit_scale = (const float*)d_in[4];
    const float* cpb_w1      = (const float*)d_in[5];
    const float* cpb_b1      = (const float*)d_in[6];
    const float* cpb_w2      = (const float*)d_in[7];
    const float* proj_w      = (const float*)d_in[8];
    const float* proj_b      = (const float*)d_in[9];
    float* out = (float*)d_out;

    __half *xh, *xl, *oh, *ol, *wq, *wp;
    cudaGetSymbolAddress((void**)&xh, g_xh);
    cudaGetSymbolAddress((void**)&xl, g_xl);
    cudaGetSymbolAddress((void**)&oh, g_oh);
    cudaGetSymbolAddress((void**)&ol, g_ol);
    cudaGetSymbolAddress((void**)&wq, g_wq);
    cudaGetSymbolAddress((void**)&wp, g_wp);

    static bool attr_set = false;
    if (!attr_set) {
        cudaFuncSetAttribute(attn_kernel,
                             cudaFuncAttributeMaxDynamicSharedMemorySize, ATTN_SMEM);
        cudaFuncSetAttribute(gemm_mma<true>,
                             cudaFuncAttributeMaxDynamicSharedMemorySize, GEMM_SMEM);
        cudaFuncSetAttribute(gemm_mma<false>,
                             cudaFuncAttributeMaxDynamicSharedMemorySize, GEMM_SMEM);
        attr_set = true;
    }

    // 0: split x (fp16 hi/lo), 1: qkv_w -> fp16, 2: proj_w -> fp16
    {
        int n4 = (M_ROWS * DIM) / 4;
        cvt_hilo4_f16<<<(n4 + 255) / 256, 256>>>((const float4*)x, (uint2*)xh, (uint2*)xl, n4);
    }
    cvt_f16_4<<<(768 * DIM / 4 + 255) / 256, 256>>>((const float4*)qkv_w,
                                                    (uint2*)wq, 768 * DIM / 4);
    cvt_f16_4<<<(DIM * DIM / 4 + 255) / 256, 256>>>((const float4*)proj_w,
                                                    (uint2*)wp, DIM * DIM / 4);

    // 3: QKV GEMM  <-- profiled launch index
    {
        dim3 grid(6, MTILES);
        gemm_mma<true><<<grid, 256, GEMM_SMEM>>>(xh, xl, wq,
                                                 nullptr, q_bias, v_bias, nullptr);
    }

    // 4: cpb, 5: rpb
    cpb_mlp_kernel<<<(TBL + 7) / 8, 256>>>(cpb_w1, cpb_b1, cpb_w2);
    rpb_kernel<<<(NH * NTOK * NTOK + 255) / 256, 256>>>();

    // 6: fused attention
    attn_kernel<<<BW * NH, 128, ATTN_SMEM>>>(logit_scale);

    // 7: proj GEMM
    {
        dim3 grid(2, MTILES);
        gemm_mma<false><<<grid, 256, GEMM_SMEM>>>(oh, ol, wp,
                                                  out, nullptr, nullptr, proj_b);
    }
}